// round 1
// baseline (speedup 1.0000x reference)
#include <cuda_runtime.h>

#define M_     32
#define N_     2048
#define D_     128
#define L_     32768
#define H_     16
#define QKV3_  6144
#define CHUNK_ 1024
#define NC_    32          // L_/CHUNK_
#define KB_    128         // keys per subtile
#define NSUB_  8           // CHUNK_/KB_

// ---------------- device scratch (no allocation allowed) ----------------
__device__ float g_scale[M_];
__device__ float g_qkv[M_ * QKV3_];
__device__ float g_num[H_ * NC_ * M_ * D_];   // 8 MB partial numerators
__device__ float g_den[H_ * NC_ * M_];        // partial denominators

typedef unsigned long long u64;

// ---------------- packed f32x2 helpers (sm_103a) ----------------
__device__ __forceinline__ u64 ffma2(u64 a, u64 b, u64 c) {
    u64 d;
    asm("fma.rn.f32x2 %0, %1, %2, %3;" : "=l"(d) : "l"(a), "l"(b), "l"(c));
    return d;
}
__device__ __forceinline__ u64 pack2(float lo, float hi) {
    u64 r;
    asm("mov.b64 %0, {%1, %2};" : "=l"(r) : "f"(lo), "f"(hi));
    return r;
}
__device__ __forceinline__ u64 dup2(float x) { return pack2(x, x); }
__device__ __forceinline__ void unpack2(u64 v, float& lo, float& hi) {
    asm("mov.b64 {%0, %1}, %2;" : "=f"(lo), "=f"(hi) : "l"(v));
}

// ---------------- kernel 1: RMSNorm row scales ----------------
__global__ void rms_kernel(const float* __restrict__ X) {
    int m = blockIdx.x;
    float s = 0.f;
    for (int k = threadIdx.x; k < N_; k += 256) {
        float v = X[m * N_ + k];
        s += v * v;
    }
    __shared__ float red[256];
    red[threadIdx.x] = s;
    __syncthreads();
    for (int o = 128; o > 0; o >>= 1) {
        if (threadIdx.x < o) red[threadIdx.x] += red[threadIdx.x + o];
        __syncthreads();
    }
    if (threadIdx.x == 0) g_scale[m] = rsqrtf(red[0] * (1.0f / N_));
}

// ---------------- kernel 2a: zero qkv (atomics target) ----------------
__global__ void zero_qkv() {
    int i = blockIdx.x * 256 + threadIdx.x;
    if (i < M_ * QKV3_) g_qkv[i] = 0.f;
}

// ---------------- kernel 2b: QKV GEMM, K-split with atomic combine ----------------
#define BN_     64
#define KC_     32
#define KSPLIT_ 4
#define KSLAB_  (N_ / KSPLIT_)   // 512

__global__ void qkv_gemm(const float* __restrict__ X, const float* __restrict__ W) {
    __shared__ float Xs[KC_][M_ + 1];   // [k][m], scaled X
    __shared__ float Ws[KC_][BN_];
    const int t  = threadIdx.x;
    const int tx = t & 31;   // col pair
    const int ty = t >> 5;   // 0..7 -> rows 4ty..4ty+3
    const int colBase = blockIdx.x * BN_;
    const int kBase0  = blockIdx.y * KSLAB_;

    u64 acc[4];
#pragma unroll
    for (int i = 0; i < 4; i++) acc[i] = 0ull;

    for (int kc = 0; kc < KSLAB_; kc += KC_) {
        const int kb = kBase0 + kc;
        __syncthreads();
        // load X chunk [M_ x KC_], coalesced along k, store transposed
#pragma unroll
        for (int i = 0; i < 4; i++) {
            int idx = t + i * 256;           // 0..1023
            int m   = idx >> 5;              // 32 rows
            int kk  = idx & 31;
            Xs[kk][m] = X[m * N_ + kb + kk] * g_scale[m];
        }
        // load W chunk [KC_ x BN_]
#pragma unroll
        for (int i = 0; i < 8; i++) {
            int idx = t + i * 256;           // 0..2047
            int kk  = idx >> 6;
            int j   = idx & 63;
            Ws[kk][j] = W[(size_t)(kb + kk) * QKV3_ + colBase + j];
        }
        __syncthreads();
#pragma unroll 4
        for (int kk = 0; kk < KC_; kk++) {
            u64 w2 = *(const u64*)&Ws[kk][2 * tx];
#pragma unroll
            for (int i = 0; i < 4; i++) {
                u64 x2 = dup2(Xs[kk][4 * ty + i]);
                acc[i] = ffma2(x2, w2, acc[i]);
            }
        }
    }
#pragma unroll
    for (int i = 0; i < 4; i++) {
        float a, b;
        unpack2(acc[i], a, b);
        int row = 4 * ty + i;
        int col = colBase + 2 * tx;
        atomicAdd(&g_qkv[row * QKV3_ + col + 0], a);
        atomicAdd(&g_qkv[row * QKV3_ + col + 1], b);
    }
}

// ---------------- kernel 3: split-KV attention partials ----------------
// smem layout (float units):
//   Qs  : [32][129]            @ 0        (4128)
//   Es  : [32][129]            @ 4128     (4128)
//   den : [32]                 @ 8256
//   KV  : union                 @ 8288
//         Kt: [128][130] (key pairs, transposed)  16640 floats
//         Vs: [128][128]                           16384 floats
#define QS_OFF   0
#define ES_OFF   4128
#define DEN_OFF  8256
#define KV_OFF   8288
#define SMEM_FLOATS (KV_OFF + D_ * (KB_ + 2))   // 8288 + 16640 = 24928
#define SMEM_BYTES  (SMEM_FLOATS * 4)           // 99712

__global__ __launch_bounds__(256, 2) void attn_partial(
    const float* __restrict__ cK,
    const float* __restrict__ cV,
    const int* __restrict__ Pp)
{
    extern __shared__ float sm[];
    float* Qs  = sm + QS_OFF;     // stride 129
    float* Es  = sm + ES_OFF;     // stride 129
    float* den = sm + DEN_OFF;
    float* KV  = sm + KV_OFF;     // Kt stride 130 / Vs stride 128

    const int h = blockIdx.y;
    const int c = blockIdx.x;
    const int P = *Pp;
    const int t  = threadIdx.x;
    const int tx = t & 15;        // 0..15
    const int ty = t >> 4;        // 0..15 -> queries {ty, ty+16}

    // stage Q for this head
#pragma unroll
    for (int i = 0; i < 16; i++) {
        int idx = t + i * 256;    // 0..4095
        int m = idx >> 7;
        int d = idx & 127;
        Qs[m * 129 + d] = g_qkv[m * QKV3_ + h * D_ + d];
    }
    if (t < 32) den[t] = 0.f;

    u64 accB[8];                  // PV accumulators: 2 queries x 4 d-pairs-of-2
#pragma unroll
    for (int j = 0; j < 8; j++) accB[j] = 0ull;
    float denacc0 = 0.f, denacc1 = 0.f;

    for (int sub = 0; sub < NSUB_; sub++) {
        const int l0 = c * CHUNK_ + sub * KB_;

        // ---- stage K subtile, transposed into key-pairs ----
        __syncthreads();
#pragma unroll
        for (int i = 0; i < 64; i++) {
            int idx = t + i * 256;      // 0..16383
            int l = idx >> 7;           // key within subtile
            int d = idx & 127;
            int gl = l0 + l;
            float v;
            if (gl >= P && gl < P + M_)
                v = g_qkv[(gl - P) * QKV3_ + N_ + h * D_ + d];       // new K
            else
                v = cK[((size_t)h * L_ + gl) * D_ + d];
            KV[d * (KB_ + 2) + l] = v;  // transposed, 2-way conflict only
        }
        __syncthreads();

        // ---- phase A: scores + exp ----
        u64 accA[8];
#pragma unroll
        for (int j = 0; j < 8; j++) accA[j] = 0ull;
        const float* Q0 = Qs + ty * 129;
        const float* Q1 = Qs + (ty + 16) * 129;
#pragma unroll 4
        for (int d = 0; d < D_; d++) {
            u64 q0 = dup2(Q0[d]);
            u64 q1 = dup2(Q1[d]);
            const float* Krow = KV + d * (KB_ + 2);
#pragma unroll
            for (int j = 0; j < 4; j++) {
                u64 kp = *(const u64*)&Krow[2 * (tx + 16 * j)];
                accA[j]     = ffma2(q0, kp, accA[j]);
                accA[4 + j] = ffma2(q1, kp, accA[4 + j]);
            }
        }
#pragma unroll
        for (int j = 0; j < 4; j++) {
            float a, b;
            int kcol = 2 * (tx + 16 * j);
            unpack2(accA[j], a, b);
            float ea = __expf(a), eb = __expf(b);
            Es[ty * 129 + kcol] = ea;
            Es[ty * 129 + kcol + 1] = eb;
            denacc0 += ea + eb;
            unpack2(accA[4 + j], a, b);
            ea = __expf(a); eb = __expf(b);
            Es[(ty + 16) * 129 + kcol] = ea;
            Es[(ty + 16) * 129 + kcol + 1] = eb;
            denacc1 += ea + eb;
        }
        __syncthreads();

        // ---- stage V subtile (overwrites Kt) ----
#pragma unroll
        for (int i = 0; i < 64; i++) {
            int idx = t + i * 256;
            int l = idx >> 7;
            int d = idx & 127;
            int gl = l0 + l;
            float v;
            if (gl >= P && gl < P + M_)
                v = g_qkv[(gl - P) * QKV3_ + 2 * N_ + h * D_ + d];   // new V
            else
                v = cV[((size_t)h * L_ + gl) * D_ + d];
            KV[l * D_ + d] = v;
        }
        __syncthreads();

        // ---- phase B: partial_out += E @ V ----
#pragma unroll 2
        for (int l = 0; l < KB_; l++) {
            u64 e0 = dup2(Es[ty * 129 + l]);
            u64 e1 = dup2(Es[(ty + 16) * 129 + l]);
            const float* Vrow = KV + l * D_;
#pragma unroll
            for (int j = 0; j < 4; j++) {
                u64 v2 = *(const u64*)&Vrow[2 * (tx + 16 * j)];
                accB[j]     = ffma2(e0, v2, accB[j]);
                accB[4 + j] = ffma2(e1, v2, accB[4 + j]);
            }
        }
    }

    // ---- write partials ----
    atomicAdd(&den[ty],      denacc0);
    atomicAdd(&den[ty + 16], denacc1);

    const size_t base0 = ((size_t)(h * NC_ + c) * M_ + ty) * D_;
    const size_t base1 = ((size_t)(h * NC_ + c) * M_ + ty + 16) * D_;
#pragma unroll
    for (int j = 0; j < 4; j++) {
        int d2 = 2 * (tx + 16 * j);
        *(u64*)&g_num[base0 + d2] = accB[j];
        *(u64*)&g_num[base1 + d2] = accB[4 + j];
    }
    __syncthreads();
    if (t < 32) g_den[(h * NC_ + c) * M_ + t] = den[t];
}

// ---------------- kernel 4: deterministic reduce + output ----------------
__global__ void reduce_out(float* __restrict__ out) {
    int hm = blockIdx.x;          // 0..511
    int h = hm >> 5;
    int m = hm & 31;
    int d = threadIdx.x;          // 0..127
    float dsum = 0.f;
#pragma unroll 8
    for (int c = 0; c < NC_; c++)
        dsum += g_den[(h * NC_ + c) * M_ + m];
    float nsum = 0.f;
#pragma unroll 8
    for (int c = 0; c < NC_; c++)
        nsum += g_num[((size_t)(h * NC_ + c) * M_ + m) * D_ + d];
    out[m * N_ + h * D_ + d] = nsum / dsum;
}

// ---------------- launch ----------------
extern "C" void kernel_launch(void* const* d_in, const int* in_sizes, int n_in,
                              void* d_out, int out_size) {
    const float* X  = (const float*)d_in[0];
    const float* W  = (const float*)d_in[1];
    const float* cK = (const float*)d_in[2];
    const float* cV = (const float*)d_in[3];
    const int*   P  = (const int*)d_in[4];
    float* out = (float*)d_out;

    cudaFuncSetAttribute(attn_partial,
                         cudaFuncAttributeMaxDynamicSharedMemorySize, SMEM_BYTES);

    rms_kernel<<<M_, 256>>>(X);
    zero_qkv<<<(M_ * QKV3_ + 255) / 256, 256>>>();
    qkv_gemm<<<dim3(QKV3_ / BN_, KSPLIT_), 256>>>(X, W);
    attn_partial<<<dim3(NC_, H_), 256, SMEM_BYTES>>>(cK, cV, P);
    reduce_out<<<H_ * M_, 128>>>(out);
}

// round 2
// speedup vs baseline: 1.2663x; 1.2663x over previous
#include <cuda_runtime.h>

#define M_     32
#define N_     2048
#define D_     128
#define L_     32768
#define H_     16
#define QKV3_  6144
#define CHUNK_ 1024
#define NC_    32          // L_/CHUNK_
#define KB_    128         // keys per subtile
#define NSUB_  8           // CHUNK_/KB_

// ---------------- device scratch (no allocation allowed) ----------------
__device__ float g_scale[M_];
__device__ float g_qkv[M_ * QKV3_];
__device__ float g_num[H_ * NC_ * M_ * D_];   // 8 MB partial numerators
__device__ float g_den[H_ * NC_ * M_];        // partial denominators

typedef unsigned long long u64;

// ---------------- packed f32x2 helpers (sm_103a) ----------------
__device__ __forceinline__ u64 ffma2(u64 a, u64 b, u64 c) {
    u64 d;
    asm("fma.rn.f32x2 %0, %1, %2, %3;" : "=l"(d) : "l"(a), "l"(b), "l"(c));
    return d;
}
__device__ __forceinline__ u64 pack2(float lo, float hi) {
    u64 r;
    asm("mov.b64 %0, {%1, %2};" : "=l"(r) : "f"(lo), "f"(hi));
    return r;
}
__device__ __forceinline__ u64 dup2(float x) { return pack2(x, x); }
__device__ __forceinline__ void unpack2(u64 v, float& lo, float& hi) {
    asm("mov.b64 {%0, %1}, %2;" : "=f"(lo), "=f"(hi) : "l"(v));
}

// ---------------- kernel 1: RMSNorm row scales ----------------
__global__ void rms_kernel(const float* __restrict__ X) {
    int m = blockIdx.x;
    float s = 0.f;
    for (int k = threadIdx.x; k < N_; k += 256) {
        float v = X[m * N_ + k];
        s += v * v;
    }
    __shared__ float red[256];
    red[threadIdx.x] = s;
    __syncthreads();
    for (int o = 128; o > 0; o >>= 1) {
        if (threadIdx.x < o) red[threadIdx.x] += red[threadIdx.x + o];
        __syncthreads();
    }
    if (threadIdx.x == 0) g_scale[m] = rsqrtf(red[0] * (1.0f / N_));
}

// ---------------- kernel 2a: zero qkv (atomics target) ----------------
__global__ void zero_qkv() {
    int i = blockIdx.x * 256 + threadIdx.x;
    if (i < M_ * QKV3_) g_qkv[i] = 0.f;
}

// ---------------- kernel 2b: QKV GEMM (8m x 2n per thread) ----------------
#define BN2_     128
#define KC2_     32
#define KSPLIT2_ 8
#define KSLAB2_  (N_ / KSPLIT2_)   // 256
#define XS_S     36

__global__ __launch_bounds__(256) void qkv_gemm(const float* __restrict__ X,
                                                const float* __restrict__ W) {
    __shared__ float Xs[KC2_ * XS_S];     // [kk][m] transposed, scaled
    __shared__ float Ws[KC2_ * BN2_];     // [kk][col]
    const int t  = threadIdx.x;
    const int mg = t >> 6;    // 0..3  -> rows mg*8 .. +8
    const int ng = t & 63;    // 0..63 -> cols 2ng, 2ng+1
    const int colBase = blockIdx.x * BN2_;
    const int kBase0  = blockIdx.y * KSLAB2_;

    u64 acc[4][2];
#pragma unroll
    for (int i = 0; i < 4; i++) { acc[i][0] = 0ull; acc[i][1] = 0ull; }

    for (int kc = 0; kc < KSLAB2_; kc += KC2_) {
        const int kb = kBase0 + kc;
        __syncthreads();
        // X chunk [32m x 32k], read coalesced, store transposed+scaled
#pragma unroll
        for (int i = 0; i < 4; i++) {
            int idx = t + i * 256;           // 0..1023
            int m   = idx >> 5;
            int kk  = idx & 31;
            Xs[kk * XS_S + m] = X[m * N_ + kb + kk] * g_scale[m];
        }
        // W chunk [32k x 128cols] as float4
#pragma unroll
        for (int i = 0; i < 4; i++) {
            int idx = t + i * 256;           // 0..1023
            int kk  = idx >> 5;
            int c4  = idx & 31;
            *(float4*)&Ws[kk * BN2_ + 4 * c4] =
                *(const float4*)&W[(size_t)(kb + kk) * QKV3_ + colBase + 4 * c4];
        }
        __syncthreads();
#pragma unroll 4
        for (int kk = 0; kk < KC2_; kk++) {
            float4 xa = *(const float4*)&Xs[kk * XS_S + mg * 8];
            float4 xb = *(const float4*)&Xs[kk * XS_S + mg * 8 + 4];
            u64 x01 = pack2(xa.x, xa.y), x23 = pack2(xa.z, xa.w);
            u64 x45 = pack2(xb.x, xb.y), x67 = pack2(xb.z, xb.w);
            u64 wv = *(const u64*)&Ws[kk * BN2_ + 2 * ng];
            float w0, w1; unpack2(wv, w0, w1);
            u64 wd0 = dup2(w0), wd1 = dup2(w1);
            acc[0][0] = ffma2(x01, wd0, acc[0][0]);
            acc[1][0] = ffma2(x23, wd0, acc[1][0]);
            acc[2][0] = ffma2(x45, wd0, acc[2][0]);
            acc[3][0] = ffma2(x67, wd0, acc[3][0]);
            acc[0][1] = ffma2(x01, wd1, acc[0][1]);
            acc[1][1] = ffma2(x23, wd1, acc[1][1]);
            acc[2][1] = ffma2(x45, wd1, acc[2][1]);
            acc[3][1] = ffma2(x67, wd1, acc[3][1]);
        }
    }
#pragma unroll
    for (int i = 0; i < 4; i++) {
#pragma unroll
        for (int j = 0; j < 2; j++) {
            float a, b;
            unpack2(acc[i][j], a, b);
            int m0  = mg * 8 + 2 * i;
            int col = colBase + 2 * ng + j;
            atomicAdd(&g_qkv[m0 * QKV3_ + col], a);
            atomicAdd(&g_qkv[(m0 + 1) * QKV3_ + col], b);
        }
    }
}

// ---------------- kernel 3: split-KV attention partials ----------------
// smem (floats):
//   Qt  [128 d][36]  (q transposed)          @ 0       4608
//   Et  [128 l][36]  (exp(scores) transposed) @ 4608    4608
//   den [32]                                  @ 9216
//   KV union:                                 @ 9248
//     Kt [128 d][130] (keys transposed)       16640
//     Vs [128 l][128] (natural)               16384
#define QT_S     36
#define ET_S     36
#define ET_OFF   4608
#define DEN_OFF  9216
#define KV_OFF   9248
#define KT_S     130
#define SMEM_FLOATS (KV_OFF + D_ * KT_S)      // 25888
#define SMEM_BYTES  (SMEM_FLOATS * 4)         // 103552

__global__ __launch_bounds__(256, 2) void attn_partial(
    const float* __restrict__ cK,
    const float* __restrict__ cV,
    const int* __restrict__ Pp)
{
    extern __shared__ float sm[];
    float* Qt  = sm;
    float* Et  = sm + ET_OFF;
    float* den = sm + DEN_OFF;
    float* KV  = sm + KV_OFF;

    const int h = blockIdx.y;
    const int c = blockIdx.x;
    const int P = *Pp;
    const int t  = threadIdx.x;
    const int qg = t >> 6;        // 0..3  -> queries qg*8 .. +8
    const int kg = t & 63;        // 0..63 -> key/d pair 2kg, 2kg+1

    // stage Q transposed for this head
#pragma unroll
    for (int i = 0; i < 16; i++) {
        int idx = t + i * 256;    // 0..4095
        int m = idx >> 7;
        int d = idx & 127;
        Qt[d * QT_S + m] = g_qkv[m * QKV3_ + h * D_ + d];
    }
    if (t < 32) den[t] = 0.f;

    u64 accB[4][2];
#pragma unroll
    for (int i = 0; i < 4; i++) { accB[i][0] = 0ull; accB[i][1] = 0ull; }
    float dreg[8];
#pragma unroll
    for (int i = 0; i < 8; i++) dreg[i] = 0.f;

    const float* Kbase = cK + (size_t)h * L_ * D_;
    const float* Vbase = cV + (size_t)h * L_ * D_;

    for (int sub = 0; sub < NSUB_; sub++) {
        const int l0 = c * CHUNK_ + sub * KB_;

        // ---- stage K transposed (l-in-warp -> conflict-free STS) ----
        __syncthreads();
#pragma unroll
        for (int i = 0; i < 16; i++) {
            int idx = t + i * 256;       // float4 index 0..4095
            int l  = idx & 127;
            int d4 = idx >> 7;           // 0..31
            int gl = l0 + l;
            float4 k4;
            if (gl >= P && gl < P + M_)
                k4 = *(const float4*)&g_qkv[(gl - P) * QKV3_ + N_ + h * D_ + 4 * d4];
            else
                k4 = *(const float4*)&Kbase[(size_t)gl * D_ + 4 * d4];
            KV[(4 * d4 + 0) * KT_S + l] = k4.x;
            KV[(4 * d4 + 1) * KT_S + l] = k4.y;
            KV[(4 * d4 + 2) * KT_S + l] = k4.z;
            KV[(4 * d4 + 3) * KT_S + l] = k4.w;
        }
        __syncthreads();

        // ---- phase A: scores (8q x 2k per thread) ----
        u64 accA[4][2];
#pragma unroll
        for (int i = 0; i < 4; i++) { accA[i][0] = 0ull; accA[i][1] = 0ull; }
#pragma unroll 2
        for (int d = 0; d < D_; d++) {
            float4 qa = *(const float4*)&Qt[d * QT_S + qg * 8];       // broadcast
            float4 qb = *(const float4*)&Qt[d * QT_S + qg * 8 + 4];   // broadcast
            u64 q01 = pack2(qa.x, qa.y), q23 = pack2(qa.z, qa.w);
            u64 q45 = pack2(qb.x, qb.y), q67 = pack2(qb.z, qb.w);
            u64 kk = *(const u64*)&KV[d * KT_S + 2 * kg];
            float k0, k1; unpack2(kk, k0, k1);
            u64 kd0 = dup2(k0), kd1 = dup2(k1);
            accA[0][0] = ffma2(q01, kd0, accA[0][0]);
            accA[1][0] = ffma2(q23, kd0, accA[1][0]);
            accA[2][0] = ffma2(q45, kd0, accA[2][0]);
            accA[3][0] = ffma2(q67, kd0, accA[3][0]);
            accA[0][1] = ffma2(q01, kd1, accA[0][1]);
            accA[1][1] = ffma2(q23, kd1, accA[1][1]);
            accA[2][1] = ffma2(q45, kd1, accA[2][1]);
            accA[3][1] = ffma2(q67, kd1, accA[3][1]);
        }
        // exp -> Et (transposed), accumulate denominators in regs
#pragma unroll
        for (int lp = 0; lp < 2; lp++) {
            float e[8];
#pragma unroll
            for (int i = 0; i < 4; i++) {
                float a, b; unpack2(accA[i][lp], a, b);
                e[2 * i]     = __expf(a);
                e[2 * i + 1] = __expf(b);
                dreg[2 * i]     += e[2 * i];
                dreg[2 * i + 1] += e[2 * i + 1];
            }
            float4 ea = make_float4(e[0], e[1], e[2], e[3]);
            float4 eb = make_float4(e[4], e[5], e[6], e[7]);
            *(float4*)&Et[(2 * kg + lp) * ET_S + qg * 8]     = ea;
            *(float4*)&Et[(2 * kg + lp) * ET_S + qg * 8 + 4] = eb;
        }
        __syncthreads();

        // ---- stage V (natural layout, coalesced) ----
#pragma unroll
        for (int i = 0; i < 16; i++) {
            int idx = t + i * 256;       // float4 index
            int l  = idx >> 5;           // 0..127
            int d4 = idx & 31;
            int gl = l0 + l;
            float4 v4;
            if (gl >= P && gl < P + M_)
                v4 = *(const float4*)&g_qkv[(gl - P) * QKV3_ + 2 * N_ + h * D_ + 4 * d4];
            else
                v4 = *(const float4*)&Vbase[(size_t)gl * D_ + 4 * d4];
            *(float4*)&KV[l * D_ + 4 * d4] = v4;
        }
        __syncthreads();

        // ---- phase B: out += E @ V (8q x 2d per thread) ----
#pragma unroll 2
        for (int l = 0; l < KB_; l++) {
            float4 ea = *(const float4*)&Et[l * ET_S + qg * 8];       // broadcast
            float4 eb = *(const float4*)&Et[l * ET_S + qg * 8 + 4];   // broadcast
            u64 e01 = pack2(ea.x, ea.y), e23 = pack2(ea.z, ea.w);
            u64 e45 = pack2(eb.x, eb.y), e67 = pack2(eb.z, eb.w);
            u64 vv = *(const u64*)&KV[l * D_ + 2 * kg];
            float v0, v1; unpack2(vv, v0, v1);
            u64 vd0 = dup2(v0), vd1 = dup2(v1);
            accB[0][0] = ffma2(e01, vd0, accB[0][0]);
            accB[1][0] = ffma2(e23, vd0, accB[1][0]);
            accB[2][0] = ffma2(e45, vd0, accB[2][0]);
            accB[3][0] = ffma2(e67, vd0, accB[3][0]);
            accB[0][1] = ffma2(e01, vd1, accB[0][1]);
            accB[1][1] = ffma2(e23, vd1, accB[1][1]);
            accB[2][1] = ffma2(e45, vd1, accB[2][1]);
            accB[3][1] = ffma2(e67, vd1, accB[3][1]);
        }
    }

    // ---- epilogue ----
#pragma unroll
    for (int i = 0; i < 8; i++) atomicAdd(&den[qg * 8 + i], dreg[i]);

    const size_t nbase = (size_t)(h * NC_ + c) * M_ * D_;
#pragma unroll
    for (int i = 0; i < 4; i++) {
        float a0, b0, a1, b1;
        unpack2(accB[i][0], a0, b0);   // d = 2kg
        unpack2(accB[i][1], a1, b1);   // d = 2kg+1
        int q0 = qg * 8 + 2 * i;
        *(u64*)&g_num[nbase + (size_t)q0 * D_ + 2 * kg]       = pack2(a0, a1);
        *(u64*)&g_num[nbase + (size_t)(q0 + 1) * D_ + 2 * kg] = pack2(b0, b1);
    }
    __syncthreads();
    if (t < 32) g_den[(h * NC_ + c) * M_ + t] = den[t];
}

// ---------------- kernel 4: deterministic reduce + output ----------------
__global__ void reduce_out(float* __restrict__ out) {
    int hm = blockIdx.x;          // 0..511
    int h = hm >> 5;
    int m = hm & 31;
    int d = threadIdx.x;          // 0..127
    float dsum = 0.f;
#pragma unroll 8
    for (int c = 0; c < NC_; c++)
        dsum += g_den[(h * NC_ + c) * M_ + m];
    float nsum = 0.f;
#pragma unroll 8
    for (int c = 0; c < NC_; c++)
        nsum += g_num[((size_t)(h * NC_ + c) * M_ + m) * D_ + d];
    out[m * N_ + h * D_ + d] = nsum / dsum;
}

// ---------------- launch ----------------
extern "C" void kernel_launch(void* const* d_in, const int* in_sizes, int n_in,
                              void* d_out, int out_size) {
    const float* X  = (const float*)d_in[0];
    const float* W  = (const float*)d_in[1];
    const float* cK = (const float*)d_in[2];
    const float* cV = (const float*)d_in[3];
    const int*   P  = (const int*)d_in[4];
    float* out = (float*)d_out;

    cudaFuncSetAttribute(attn_partial,
                         cudaFuncAttributeMaxDynamicSharedMemorySize, SMEM_BYTES);

    rms_kernel<<<M_, 256>>>(X);
    zero_qkv<<<(M_ * QKV3_ + 255) / 256, 256>>>();
    qkv_gemm<<<dim3(QKV3_ / BN2_, KSPLIT2_), 256>>>(X, W);
    attn_partial<<<dim3(NC_, H_), 256, SMEM_BYTES>>>(cK, cV, P);
    reduce_out<<<H_ * M_, 128>>>(out);
}